// round 6
// baseline (speedup 1.0000x reference)
#include <cuda_runtime.h>
#include <cstdint>

#define B     16
#define C     96
#define HW    50176
#define HW4   12544
#define KSEL  25088
#define CHUNKS 3
#define CPT   32       // channels per chunk
#define NB11  2048     // radix bins (11 bits)
#define BPB   49       // blocks per batch in combine (49*256 = HW4)

// Scratch (no allocs allowed).
__device__ float        g_part[CHUNKS * B * HW];   // 9.6 MB partial energies
__device__ float        g_e2[B * HW];              // 3.2 MB combined energy^2
__device__ unsigned int g_hist[B * NB11];          // 128 KB per-batch hist (bits 31:21)
__device__ unsigned int g_maskbits[B * HW / 32];   // 100 KB

// ---------------------------------------------------------------------------
// Pass 1: partial energy over 32-channel chunks (HBM roofline, measured 47us).
// Also zeroes the global hist for this graph replay (runs first).
// ---------------------------------------------------------------------------
__global__ void energy_kernel(const float4* __restrict__ x) {
    int idx = blockIdx.x * blockDim.x + threadIdx.x;      // over CHUNKS*B*HW4
    if (idx < B * NB11 / 4) {
        uint4 z; z.x = z.y = z.z = z.w = 0u;
        reinterpret_cast<uint4*>(g_hist)[idx] = z;
    }
    if (idx >= CHUNKS * B * HW4) return;
    int chunk = idx / (B * HW4);
    int r     = idx - chunk * (B * HW4);
    int b     = r / HW4;
    int p     = r - b * HW4;
    const float4* base = x + (size_t)b * (C * HW4) + (size_t)(chunk * CPT) * HW4 + p;
    float ax = 0.f, ay = 0.f, az = 0.f, aw = 0.f;
#pragma unroll 16
    for (int c = 0; c < CPT; c++) {
        float4 v = __ldcs(base + (size_t)c * HW4);
        ax += v.x * v.x; ay += v.y * v.y; az += v.z * v.z; aw += v.w * v.w;
    }
    float4 o; o.x = ax; o.y = ay; o.z = az; o.w = aw;
    reinterpret_cast<float4*>(g_part)[idx] = o;
}

// ---------------------------------------------------------------------------
// Pass 2 (wide): combine partials -> e2, smem-histogram bits 31:21, merge
// nonzero bins to the per-batch global hist. energy2 >= 0 => uint order ==
// float order. Warps never straddle batches.
// ---------------------------------------------------------------------------
__global__ void combine_hist_kernel() {
    __shared__ unsigned int hist[NB11];
    int b   = blockIdx.x / BPB;
    int blk = blockIdx.x % BPB;
    int tid = threadIdx.x;
    for (int i = tid; i < NB11; i += 256) hist[i] = 0;
    __syncthreads();

    int idx = b * HW4 + blk * 256 + tid;                  // float4 index
    const float4* part = reinterpret_cast<const float4*>(g_part);
    float4 a  = part[idx];
    float4 p1 = part[idx + B * HW4];
    float4 p2 = part[idx + 2 * B * HW4];
    float4 e;
    e.x = a.x + p1.x + p2.x;
    e.y = a.y + p1.y + p2.y;
    e.z = a.z + p1.z + p2.z;
    e.w = a.w + p1.w + p2.w;
    reinterpret_cast<float4*>(g_e2)[idx] = e;
#pragma unroll
    for (int j = 0; j < 4; j++) {
        float f = (j == 0) ? e.x : (j == 1) ? e.y : (j == 2) ? e.z : e.w;
        unsigned int dig = __float_as_uint(f) >> 21;
        unsigned int m = __match_any_sync(0xFFFFFFFFu, dig);
        if ((int)(tid & 31) == (__ffs(m) - 1))
            atomicAdd(&hist[dig], (unsigned)__popc(m));
    }
    __syncthreads();

    unsigned int* gh = g_hist + b * NB11;
    for (int i = tid; i < NB11; i += 256) {
        unsigned int v = hist[i];
        if (v) atomicAdd(&gh[i], v);
    }
}

// ---------------------------------------------------------------------------
// Helper: block-wide suffix scan over ss[1024] (Hillis-Steele).
// ---------------------------------------------------------------------------
__device__ __forceinline__ void suffix_scan(unsigned int* ss, int tid) {
    for (int off = 1; off < 1024; off <<= 1) {
        unsigned int v = (tid + off < 1024) ? ss[tid + off] : 0u;
        __syncthreads();
        ss[tid] += v;
        __syncthreads();
    }
}

// ---------------------------------------------------------------------------
// Pass 3 (fused select): per batch, find exact k-th-largest key by refining
// the 11-bit global-hist bin with two more radix stages (bits 20:10, 9:0),
// then ballot-pack the mask. One block per batch, 1024 threads.
// All key sweeps hit L2 (e2 is 3.2 MB, just written).
// ---------------------------------------------------------------------------
__global__ void select_kernel() {
    __shared__ unsigned int hist[NB11];
    __shared__ unsigned int ss[1024];
    __shared__ unsigned int s_val[2];                      // {bin, remk}
    int b   = blockIdx.x;
    int tid = threadIdx.x;
    const unsigned int* keys  = reinterpret_cast<const unsigned int*>(g_e2) + b * HW;
    const uint4*        keys4 = reinterpret_cast<const uint4*>(keys);

    // --- Stage 1: pick 11-bit top prefix from the global histogram. ---
    {
        const unsigned int* gh = g_hist + b * NB11;
        unsigned int h0 = gh[2 * tid], h1 = gh[2 * tid + 1];
        ss[tid] = h0 + h1;
        __syncthreads();
        suffix_scan(ss, tid);
        unsigned int ss_next = (tid + 1 < 1024) ? ss[tid + 1] : 0u;
        unsigned int S1 = ss_next + h1;
        unsigned int S0 = S1 + h0;
        unsigned int S2 = ss_next;
        if (S1 >= KSEL && S2 < KSEL) { s_val[0] = 2u * tid + 1u; s_val[1] = KSEL - S2; }
        if (S0 >= KSEL && S1 < KSEL) { s_val[0] = 2u * tid;      s_val[1] = KSEL - S1; }
    }
    __syncthreads();
    unsigned int prefix = s_val[0];
    unsigned int remk   = s_val[1];
    __syncthreads();

    // --- Stage 2: histogram bits 20:10 among keys matching the prefix. ---
    hist[tid] = 0; hist[tid + 1024] = 0;
    __syncthreads();
    // HW4 = 12*1024 + 256 : last partial iteration covers warps 0..7 fully.
    for (int i = tid; i < HW4; i += 1024) {
        uint4 kv = keys4[i];
#pragma unroll
        for (int j = 0; j < 4; j++) {
            unsigned int key = (j == 0) ? kv.x : (j == 1) ? kv.y : (j == 2) ? kv.z : kv.w;
            unsigned int dig = ((key >> 21) == prefix) ? ((key >> 10) & 2047u)
                                                       : 0xFFFFFFFFu;
            unsigned int m = __match_any_sync(0xFFFFFFFFu, dig);
            if (dig != 0xFFFFFFFFu && (int)(tid & 31) == (__ffs(m) - 1))
                atomicAdd(&hist[dig], (unsigned)__popc(m));
        }
    }
    __syncthreads();
    {
        unsigned int h0 = hist[2 * tid], h1 = hist[2 * tid + 1];
        ss[tid] = h0 + h1;
        __syncthreads();
        suffix_scan(ss, tid);
        unsigned int ss_next = (tid + 1 < 1024) ? ss[tid + 1] : 0u;
        unsigned int S1 = ss_next + h1;
        unsigned int S0 = S1 + h0;
        unsigned int S2 = ss_next;
        if (S1 >= remk && S2 < remk) { s_val[0] = 2u * tid + 1u; s_val[1] = remk - S2; }
        if (S0 >= remk && S1 < remk) { s_val[0] = 2u * tid;      s_val[1] = remk - S1; }
    }
    __syncthreads();
    unsigned int pref21 = (prefix << 11) | s_val[0];       // bits 31:10 fixed
    remk = s_val[1];
    __syncthreads();

    // --- Stage 3: histogram bits 9:0 among keys matching pref21. ---
    hist[tid] = 0;
    __syncthreads();
    for (int i = tid; i < HW4; i += 1024) {
        uint4 kv = keys4[i];
#pragma unroll
        for (int j = 0; j < 4; j++) {
            unsigned int key = (j == 0) ? kv.x : (j == 1) ? kv.y : (j == 2) ? kv.z : kv.w;
            unsigned int dig = ((key >> 10) == pref21) ? (key & 1023u) : 0xFFFFFFFFu;
            unsigned int m = __match_any_sync(0xFFFFFFFFu, dig);
            if (dig != 0xFFFFFFFFu && (int)(tid & 31) == (__ffs(m) - 1))
                atomicAdd(&hist[dig], (unsigned)__popc(m));
        }
    }
    __syncthreads();
    {
        ss[tid] = hist[tid];
        __syncthreads();
        suffix_scan(ss, tid);
        unsigned int below = (tid + 1 < 1024) ? ss[tid + 1] : 0u;
        if (ss[tid] >= remk && below < remk)
            s_val[0] = (pref21 << 10) | (unsigned)tid;      // exact threshold
    }
    __syncthreads();
    unsigned int t = s_val[0];

    // --- Stage 4: ballot-pack mask bits (49 exact iterations). ---
    for (int i = tid; i < HW; i += 1024) {
        unsigned int key = keys[i];
        unsigned int bal = __ballot_sync(0xFFFFFFFFu, key >= t);
        if ((tid & 31) == 0) g_maskbits[(b * HW + i) >> 5] = bal;
    }
}

// ---------------------------------------------------------------------------
// Pass 4: out = x * mask (HBM roofline, measured ~90us).
// ---------------------------------------------------------------------------
__global__ void mask_kernel(const float4* __restrict__ x, float4* __restrict__ out) {
    int t = blockIdx.x * blockDim.x + threadIdx.x;        // over B*C*HW4/2
    if (t >= B * C * HW4 / 2) return;
    int idx = t * 2;
    int b  = idx / (C * HW4);
    int p  = idx % HW4;
    int hw = p * 4;
    unsigned int bits = g_maskbits[((unsigned)(b * HW + hw)) >> 5] >> (hw & 31);
    float4 v0 = __ldcs(x + (size_t)idx);
    float4 v1 = __ldcs(x + (size_t)idx + 1);
    float4 r0, r1;
    r0.x = (bits &   1u) ? v0.x : 0.f;
    r0.y = (bits &   2u) ? v0.y : 0.f;
    r0.z = (bits &   4u) ? v0.z : 0.f;
    r0.w = (bits &   8u) ? v0.w : 0.f;
    r1.x = (bits &  16u) ? v1.x : 0.f;
    r1.y = (bits &  32u) ? v1.y : 0.f;
    r1.z = (bits &  64u) ? v1.z : 0.f;
    r1.w = (bits & 128u) ? v1.w : 0.f;
    __stcs(out + (size_t)idx,     r0);
    __stcs(out + (size_t)idx + 1, r1);
}

extern "C" void kernel_launch(void* const* d_in, const int* in_sizes, int n_in,
                              void* d_out, int out_size) {
    const float* x = (const float*)d_in[0];
    float*     out = (float*)d_out;

    energy_kernel<<<(CHUNKS * B * HW4) / 256, 256>>>((const float4*)x);
    combine_hist_kernel<<<B * BPB, 256>>>();
    select_kernel<<<B, 1024>>>();
    mask_kernel<<<(B * C * HW4 / 2 + 255) / 256, 256>>>((const float4*)x, (float4*)out);
}